// round 2
// baseline (speedup 1.0000x reference)
#include <cuda_runtime.h>
#include <math.h>

#define BB 4
#define NN 128
#define LL 20
#define DD 512
#define SCALE 0.044194173824159216f  // 1/sqrt(512)

// -------- scratch (device globals; no allocation allowed) --------
__device__ float g_q[BB * NN * DD];      // q projection  [B,N,D]
__device__ float g_k[BB * LL * DD];      // k projection  [B,L,D]
__device__ float g_fbq[BB * NN * DD];    // gated boundary features
__device__ float g_S[BB * NN * NN];      // A_b logits (pre-softmax, scaled)
__device__ float g_A[BB * NN * NN];      // A_b (post-softmax)
__device__ float g_fbb[BB * NN * DD];    // A_b @ f_b

// =====================================================================
// K1: fused projections  q = f_b@Wq^T+bq  (rows 0..511),  k = f_w@Wk^T+bk
// BM=BN=32, BK=16, 64 threads, 4x4 per thread.
// grid: (16 ntiles, 19 mtiles): mtile<16 -> q, else k (80 rows, guarded)
// =====================================================================
__global__ void proj_kernel(const float* __restrict__ Xq, const float* __restrict__ Xk,
                            const float* __restrict__ Wq, const float* __restrict__ bq,
                            const float* __restrict__ Wk, const float* __restrict__ bk)
{
    const int ntile = blockIdx.x, mtile = blockIdx.y;
    const float *X, *W, *bias;
    float* C;
    int Mrows, row0;
    if (mtile < 16) { X = Xq; W = Wq; bias = bq; C = g_q; Mrows = BB * NN; row0 = mtile * 32; }
    else            { X = Xk; W = Wk; bias = bk; C = g_k; Mrows = BB * LL; row0 = (mtile - 16) * 32; }
    const int n0 = ntile * 32;

    __shared__ float As[16][36];
    __shared__ float Bs[16][36];
    const int tid = threadIdx.x;
    const int tx = tid & 7, ty = tid >> 3;
    const int lm = tid >> 1, lk = (tid & 1) * 8;

    float acc[4][4] = {};

    for (int k0 = 0; k0 < DD; k0 += 16) {
        float4 a0, a1;
        const int gr = row0 + lm;
        if (gr < Mrows) {
            a0 = *(const float4*)&X[gr * DD + k0 + lk];
            a1 = *(const float4*)&X[gr * DD + k0 + lk + 4];
        } else {
            a0 = make_float4(0.f, 0.f, 0.f, 0.f);
            a1 = a0;
        }
        As[lk + 0][lm] = a0.x; As[lk + 1][lm] = a0.y; As[lk + 2][lm] = a0.z; As[lk + 3][lm] = a0.w;
        As[lk + 4][lm] = a1.x; As[lk + 5][lm] = a1.y; As[lk + 6][lm] = a1.z; As[lk + 7][lm] = a1.w;

        const float4 b0 = *(const float4*)&W[(n0 + lm) * DD + k0 + lk];
        const float4 b1 = *(const float4*)&W[(n0 + lm) * DD + k0 + lk + 4];
        Bs[lk + 0][lm] = b0.x; Bs[lk + 1][lm] = b0.y; Bs[lk + 2][lm] = b0.z; Bs[lk + 3][lm] = b0.w;
        Bs[lk + 4][lm] = b1.x; Bs[lk + 5][lm] = b1.y; Bs[lk + 6][lm] = b1.z; Bs[lk + 7][lm] = b1.w;
        __syncthreads();

#pragma unroll
        for (int k = 0; k < 16; k++) {
            const float4 a = *(const float4*)&As[k][ty * 4];
            const float4 b = *(const float4*)&Bs[k][tx * 4];
            acc[0][0] += a.x * b.x; acc[0][1] += a.x * b.y; acc[0][2] += a.x * b.z; acc[0][3] += a.x * b.w;
            acc[1][0] += a.y * b.x; acc[1][1] += a.y * b.y; acc[1][2] += a.y * b.z; acc[1][3] += a.y * b.w;
            acc[2][0] += a.z * b.x; acc[2][1] += a.z * b.y; acc[2][2] += a.z * b.z; acc[2][3] += a.z * b.w;
            acc[3][0] += a.w * b.x; acc[3][1] += a.w * b.y; acc[3][2] += a.w * b.z; acc[3][3] += a.w * b.w;
        }
        __syncthreads();
    }

    const float4 bv = *(const float4*)&bias[n0 + tx * 4];
#pragma unroll
    for (int i = 0; i < 4; i++) {
        const int m = row0 + ty * 4 + i;
        if (m < Mrows) {
            float4 o;
            o.x = acc[i][0] + bv.x; o.y = acc[i][1] + bv.y;
            o.z = acc[i][2] + bv.z; o.w = acc[i][3] + bv.w;
            *(float4*)&C[m * DD + n0 + tx * 4] = o;
        }
    }
}

// =====================================================================
// K2: fused cross-attention + sentence gate.  One block per (b, n).
// logits[l] = q[b,n]·k[b,l]*scale ; softmax over L=20 ;
// f_bq = f_b * (attn@f_w + f_s)
// =====================================================================
__global__ void cross_attn_kernel(const float* __restrict__ f_b,
                                  const float* __restrict__ f_w,
                                  const float* __restrict__ f_s)
{
    const int n = blockIdx.x, b = blockIdx.y;
    __shared__ float qs[DD];
    __shared__ float logit[24];
    __shared__ float attn[24];
    const int tid = threadIdx.x;  // 256
    const int w = tid >> 5, lane = tid & 31;

    const float* qrow = &g_q[(b * NN + n) * DD];
    for (int d = tid; d < DD; d += 256) qs[d] = qrow[d];
    __syncthreads();

    for (int l = w; l < LL; l += 8) {
        const float* krow = &g_k[(b * LL + l) * DD];
        float s = 0.f;
        for (int d = lane; d < DD; d += 32) s += qs[d] * krow[d];
#pragma unroll
        for (int o = 16; o > 0; o >>= 1) s += __shfl_xor_sync(0xffffffffu, s, o);
        if (lane == 0) logit[l] = s * SCALE;
    }
    __syncthreads();

    if (tid == 0) {
        float mx = -1e30f;
#pragma unroll
        for (int l = 0; l < LL; l++) mx = fmaxf(mx, logit[l]);
        float sum = 0.f;
#pragma unroll
        for (int l = 0; l < LL; l++) { const float e = __expf(logit[l] - mx); attn[l] = e; sum += e; }
        const float inv = 1.f / sum;
#pragma unroll
        for (int l = 0; l < LL; l++) attn[l] *= inv;
    }
    __syncthreads();

    for (int d = tid; d < DD; d += 256) {
        float acc = 0.f;
#pragma unroll
        for (int l = 0; l < LL; l++) acc += attn[l] * f_w[(b * LL + l) * DD + d];
        const float v = f_b[(b * NN + n) * DD + d] * (acc + f_s[b * DD + d]);
        g_fbq[(b * NN + n) * DD + d] = v;
    }
}

// =====================================================================
// K3: A_b logits = scale * f_bq @ f_bq^T  (per batch 128x128x512)
// BM=BN=32, BK=16, 64 threads, 4x4 per thread. grid (4,4,B)
// =====================================================================
__global__ void ab_logits_kernel()
{
    const int b = blockIdx.z;
    const float* X = &g_fbq[b * NN * DD];
    const int r0 = blockIdx.y * 32;   // row (n) tile
    const int c0 = blockIdx.x * 32;   // col (m) tile

    __shared__ float As[16][36];
    __shared__ float Bs[16][36];
    const int tid = threadIdx.x;
    const int tx = tid & 7, ty = tid >> 3;
    const int lm = tid >> 1, lk = (tid & 1) * 8;

    float acc[4][4] = {};

    for (int k0 = 0; k0 < DD; k0 += 16) {
        const float4 a0 = *(const float4*)&X[(r0 + lm) * DD + k0 + lk];
        const float4 a1 = *(const float4*)&X[(r0 + lm) * DD + k0 + lk + 4];
        As[lk + 0][lm] = a0.x; As[lk + 1][lm] = a0.y; As[lk + 2][lm] = a0.z; As[lk + 3][lm] = a0.w;
        As[lk + 4][lm] = a1.x; As[lk + 5][lm] = a1.y; As[lk + 6][lm] = a1.z; As[lk + 7][lm] = a1.w;
        const float4 b0 = *(const float4*)&X[(c0 + lm) * DD + k0 + lk];
        const float4 b1 = *(const float4*)&X[(c0 + lm) * DD + k0 + lk + 4];
        Bs[lk + 0][lm] = b0.x; Bs[lk + 1][lm] = b0.y; Bs[lk + 2][lm] = b0.z; Bs[lk + 3][lm] = b0.w;
        Bs[lk + 4][lm] = b1.x; Bs[lk + 5][lm] = b1.y; Bs[lk + 6][lm] = b1.z; Bs[lk + 7][lm] = b1.w;
        __syncthreads();

#pragma unroll
        for (int k = 0; k < 16; k++) {
            const float4 a = *(const float4*)&As[k][ty * 4];
            const float4 v = *(const float4*)&Bs[k][tx * 4];
            acc[0][0] += a.x * v.x; acc[0][1] += a.x * v.y; acc[0][2] += a.x * v.z; acc[0][3] += a.x * v.w;
            acc[1][0] += a.y * v.x; acc[1][1] += a.y * v.y; acc[1][2] += a.y * v.z; acc[1][3] += a.y * v.w;
            acc[2][0] += a.z * v.x; acc[2][1] += a.z * v.y; acc[2][2] += a.z * v.z; acc[2][3] += a.z * v.w;
            acc[3][0] += a.w * v.x; acc[3][1] += a.w * v.y; acc[3][2] += a.w * v.z; acc[3][3] += a.w * v.w;
        }
        __syncthreads();
    }

#pragma unroll
    for (int i = 0; i < 4; i++) {
        float4 o;
        o.x = acc[i][0] * SCALE; o.y = acc[i][1] * SCALE;
        o.z = acc[i][2] * SCALE; o.w = acc[i][3] * SCALE;
        *(float4*)&g_S[b * NN * NN + (r0 + ty * 4 + i) * NN + c0 + tx * 4] = o;
    }
}

// =====================================================================
// K4: row softmax over m (128).  grid = B*N blocks, 128 threads.
// =====================================================================
__global__ void softmax_kernel()
{
    const int row = blockIdx.x;
    const int tid = threadIdx.x;
    const int w = tid >> 5, lane = tid & 31;
    __shared__ float red[4];

    const float v = g_S[row * NN + tid];
    float m = v;
#pragma unroll
    for (int o = 16; o > 0; o >>= 1) m = fmaxf(m, __shfl_xor_sync(0xffffffffu, m, o));
    if (lane == 0) red[w] = m;
    __syncthreads();
    m = fmaxf(fmaxf(red[0], red[1]), fmaxf(red[2], red[3]));
    __syncthreads();

    const float e = __expf(v - m);
    float s = e;
#pragma unroll
    for (int o = 16; o > 0; o >>= 1) s += __shfl_xor_sync(0xffffffffu, s, o);
    if (lane == 0) red[w] = s;
    __syncthreads();
    s = red[0] + red[1] + red[2] + red[3];

    g_A[row * NN + tid] = e / s;
}

// =====================================================================
// K5: f_bb = A_b @ f_b  (per batch 128x512x128)
// BM=32(n), BN=64(d), BK=16(m), 256 threads, 2x4 per thread. grid (8,4,B)
// =====================================================================
__global__ void fbb_kernel(const float* __restrict__ f_b)
{
    const int b = blockIdx.z;
    const int n0 = blockIdx.y * 32;
    const int d0 = blockIdx.x * 64;

    __shared__ float As[16][36];   // [m][n]
    __shared__ float Bs[16][68];   // [m][d]
    const int tid = threadIdx.x;   // 256
    const int tx = tid & 15, ty = tid >> 4;

    float acc[2][4] = {};

    const int ln = tid >> 3, lk2 = (tid & 7) * 2;   // A loader: 32 rows x 16 m
    const int br = tid >> 4, bc = (tid & 15) * 4;   // B loader: 16 rows x 64 d

    for (int k0 = 0; k0 < NN; k0 += 16) {
        const float2 a2 = *(const float2*)&g_A[(b * NN + n0 + ln) * NN + k0 + lk2];
        As[lk2][ln] = a2.x; As[lk2 + 1][ln] = a2.y;
        const float4 b4 = *(const float4*)&f_b[(b * NN + k0 + br) * DD + d0 + bc];
        *(float4*)&Bs[br][bc] = b4;
        __syncthreads();

#pragma unroll
        for (int m = 0; m < 16; m++) {
            const float2 a = *(const float2*)&As[m][ty * 2];
            const float4 v = *(const float4*)&Bs[m][tx * 4];
            acc[0][0] += a.x * v.x; acc[0][1] += a.x * v.y; acc[0][2] += a.x * v.z; acc[0][3] += a.x * v.w;
            acc[1][0] += a.y * v.x; acc[1][1] += a.y * v.y; acc[1][2] += a.y * v.z; acc[1][3] += a.y * v.w;
        }
        __syncthreads();
    }

#pragma unroll
    for (int i = 0; i < 2; i++) {
        float4 o;
        o.x = acc[i][0]; o.y = acc[i][1]; o.z = acc[i][2]; o.w = acc[i][3];
        *(float4*)&g_fbb[(b * NN + n0 + ty * 2 + i) * DD + d0 + tx * 4] = o;
    }
}

// =====================================================================
// K6: streaming f_m reduction + residual + f_bb.
// out[b,j,d] = sum_i acol[i]*sigmoid(fm*fs)*fm  +  f_b[b,j,d] + f_bb[b,j,d]
// One block per (j, b); 256 threads, 2 d's each; coalesced over d.
// =====================================================================
__global__ void final_kernel(const float* __restrict__ f_b,
                             const float* __restrict__ f_s,
                             const float* __restrict__ f_m,
                             float* __restrict__ out)
{
    const int j = blockIdx.x, b = blockIdx.y;
    __shared__ float acol[NN];
    const int tid = threadIdx.x;  // 256
    if (tid < NN) acol[tid] = g_A[b * NN * NN + tid * NN + j];
    __syncthreads();

    const int d0 = tid, d1 = tid + 256;
    const float fs0 = f_s[b * DD + d0];
    const float fs1 = f_s[b * DD + d1];
    float acc0 = 0.f, acc1 = 0.f;

    const float* fm = &f_m[((size_t)(b * NN * NN) + j) * DD];
#pragma unroll 4
    for (int i = 0; i < NN; i++) {
        const float a = acol[i];
        const float v0 = fm[(size_t)i * NN * DD + d0];
        const float v1 = fm[(size_t)i * NN * DD + d1];
        const float g0 = 1.f / (1.f + __expf(-v0 * fs0));
        const float g1 = 1.f / (1.f + __expf(-v1 * fs1));
        acc0 += a * g0 * v0;
        acc1 += a * g1 * v1;
    }

    const size_t o = (size_t)(b * NN + j) * DD;
    out[o + d0] = acc0 + f_b[o + d0] + g_fbb[o + d0];
    out[o + d1] = acc1 + f_b[o + d1] + g_fbb[o + d1];
}

// =====================================================================
extern "C" void kernel_launch(void* const* d_in, const int* in_sizes, int n_in,
                              void* d_out, int out_size)
{
    const float* f_b = (const float*)d_in[0];
    const float* f_w = (const float*)d_in[1];
    const float* f_s = (const float*)d_in[2];
    const float* f_m = (const float*)d_in[3];
    const float* Wq  = (const float*)d_in[4];
    const float* bq  = (const float*)d_in[5];
    const float* Wk  = (const float*)d_in[6];
    const float* bk  = (const float*)d_in[7];
    float* out = (float*)d_out;

    proj_kernel<<<dim3(16, 19), 64>>>(f_b, f_w, Wq, bq, Wk, bk);
    cross_attn_kernel<<<dim3(NN, BB), 256>>>(f_b, f_w, f_s);
    ab_logits_kernel<<<dim3(4, 4, BB), 64>>>();
    softmax_kernel<<<BB * NN, NN>>>();
    fbb_kernel<<<dim3(8, 4, BB), 256>>>(f_b);
    final_kernel<<<dim3(NN, BB), 256>>>(f_b, f_s, f_m, out);
}

// round 3
// speedup vs baseline: 1.3025x; 1.3025x over previous
#include <cuda_runtime.h>
#include <math.h>

#define BB 4
#define NN 128
#define LL 20
#define DD 512
#define SCALE 0.044194173824159216f  // 1/sqrt(512)

// -------- scratch (device globals; no allocation allowed) --------
__device__ float g_q[BB * NN * DD];      // q projection  [B,N,D]
__device__ float g_k[BB * LL * DD];      // k projection  [B,L,D]
__device__ float g_fbq[BB * NN * DD];    // gated boundary features
__device__ float g_S[BB * NN * NN];      // A_b logits (pre-softmax, scaled)
__device__ float g_A[BB * NN * NN];      // A_b (post-softmax)
__device__ float g_fbb[BB * NN * DD];    // A_b @ f_b

// packed fp32x2 FMA (Blackwell FFMA2)
__device__ __forceinline__ float2 ffma2(float2 a, float2 b, float2 c) {
    float2 d;
    asm("fma.rn.f32x2 %0, %1, %2, %3;"
        : "=l"(reinterpret_cast<unsigned long long&>(d))
        : "l"(reinterpret_cast<unsigned long long&>(a)),
          "l"(reinterpret_cast<unsigned long long&>(b)),
          "l"(reinterpret_cast<unsigned long long&>(c)));
    return d;
}

// =====================================================================
// K1: fused projections  q = f_b@Wq^T+bq,  k = f_w@Wk^T+bk
// BM=64, BN=32, BK=16, 256 threads, FFMA2 with duplicated-A smem.
// grid (16 ntiles, 10 mtiles): mtile<8 -> q (512 rows), else k (80 rows)
// =====================================================================
__global__ void __launch_bounds__(256) proj_kernel(
    const float* __restrict__ Xq, const float* __restrict__ Xk,
    const float* __restrict__ Wq, const float* __restrict__ bq,
    const float* __restrict__ Wk, const float* __restrict__ bk)
{
    const int ntile = blockIdx.x, mtile = blockIdx.y;
    const float *X, *W, *bias;
    float* C;
    int Mrows, row0;
    if (mtile < 8) { X = Xq; W = Wq; bias = bq; C = g_q; Mrows = BB * NN; row0 = mtile * 64; }
    else           { X = Xk; W = Wk; bias = bk; C = g_k; Mrows = BB * LL; row0 = (mtile - 8) * 64; }
    const int n0 = ntile * 32;

    __shared__ __align__(16) float Ad[16][132];  // duplicated: Ad[k][2m]=Ad[k][2m+1]=A[m][k]
    __shared__ __align__(16) float Bs[16][36];   // Bs[k][n]

    const int tid = threadIdx.x;
    const int tx = tid & 15;        // n-pair 0..15 (covers 32 n as 16 pairs)
    const int ty = tid >> 4;        // m-group 0..15 (4 rows each)

    const int ar = tid >> 2;        // A loader row 0..63
    const int ak = (tid & 3) * 4;   // A loader k offset
    const bool avalid = (row0 + ar) < Mrows;
    const int br = tid >> 2;        // B loader (tid<128): row 0..31
    const int bk2 = (tid & 3) * 4;

    float2 acc[4] = {};

    for (int k0 = 0; k0 < DD; k0 += 16) {
        float4 av = make_float4(0.f, 0.f, 0.f, 0.f);
        if (avalid) av = *(const float4*)&X[(row0 + ar) * DD + k0 + ak];
        {
            float2 d0 = make_float2(av.x, av.x);
            float2 d1 = make_float2(av.y, av.y);
            float2 d2 = make_float2(av.z, av.z);
            float2 d3 = make_float2(av.w, av.w);
            *(float2*)&Ad[ak + 0][2 * ar] = d0;
            *(float2*)&Ad[ak + 1][2 * ar] = d1;
            *(float2*)&Ad[ak + 2][2 * ar] = d2;
            *(float2*)&Ad[ak + 3][2 * ar] = d3;
        }
        if (tid < 128) {
            const float4 bv = *(const float4*)&W[(n0 + br) * DD + k0 + bk2];
            Bs[bk2 + 0][br] = bv.x; Bs[bk2 + 1][br] = bv.y;
            Bs[bk2 + 2][br] = bv.z; Bs[bk2 + 3][br] = bv.w;
        }
        __syncthreads();

#pragma unroll
        for (int k = 0; k < 16; k++) {
            const float4 ad0 = *(const float4*)&Ad[k][ty * 8];
            const float4 ad1 = *(const float4*)&Ad[k][ty * 8 + 4];
            const float2 b2  = *(const float2*)&Bs[k][tx * 2];
            acc[0] = ffma2(make_float2(ad0.x, ad0.y), b2, acc[0]);
            acc[1] = ffma2(make_float2(ad0.z, ad0.w), b2, acc[1]);
            acc[2] = ffma2(make_float2(ad1.x, ad1.y), b2, acc[2]);
            acc[3] = ffma2(make_float2(ad1.z, ad1.w), b2, acc[3]);
        }
        __syncthreads();
    }

    const float2 bv2 = *(const float2*)&bias[n0 + tx * 2];
#pragma unroll
    for (int i = 0; i < 4; i++) {
        const int m = row0 + ty * 4 + i;
        if (m < Mrows) {
            float2 o;
            o.x = acc[i].x + bv2.x;
            o.y = acc[i].y + bv2.y;
            *(float2*)&C[m * DD + n0 + tx * 2] = o;
        }
    }
}

// =====================================================================
// K2: fused cross-attention + sentence gate.  One block per (b, n).
// =====================================================================
__global__ void __launch_bounds__(256) cross_attn_kernel(
    const float* __restrict__ f_b, const float* __restrict__ f_w,
    const float* __restrict__ f_s)
{
    const int n = blockIdx.x, b = blockIdx.y;
    __shared__ float qs[DD];
    __shared__ float logit[24];
    __shared__ float attn[24];
    const int tid = threadIdx.x;  // 256
    const int w = tid >> 5, lane = tid & 31;

    const float* qrow = &g_q[(b * NN + n) * DD];
    for (int d = tid; d < DD; d += 256) qs[d] = qrow[d];
    __syncthreads();

    for (int l = w; l < LL; l += 8) {
        const float* krow = &g_k[(b * LL + l) * DD];
        float s = 0.f;
        for (int d = lane; d < DD; d += 32) s += qs[d] * krow[d];
#pragma unroll
        for (int o = 16; o > 0; o >>= 1) s += __shfl_xor_sync(0xffffffffu, s, o);
        if (lane == 0) logit[l] = s * SCALE;
    }
    __syncthreads();

    if (tid < 32) {
        float lg = (tid < LL) ? logit[tid] : -1e30f;
        float mx = lg;
#pragma unroll
        for (int o = 16; o > 0; o >>= 1) mx = fmaxf(mx, __shfl_xor_sync(0xffffffffu, mx, o));
        float e = (tid < LL) ? __expf(lg - mx) : 0.f;
        float s = e;
#pragma unroll
        for (int o = 16; o > 0; o >>= 1) s += __shfl_xor_sync(0xffffffffu, s, o);
        if (tid < LL) attn[tid] = e / s;
    }
    __syncthreads();

    for (int d = tid; d < DD; d += 256) {
        float acc = 0.f;
#pragma unroll
        for (int l = 0; l < LL; l++) acc += attn[l] * f_w[(b * LL + l) * DD + d];
        const float v = f_b[(b * NN + n) * DD + d] * (acc + f_s[b * DD + d]);
        g_fbq[(b * NN + n) * DD + d] = v;
    }
}

// =====================================================================
// K3: A_b logits = scale * f_bq @ f_bq^T  — SYMMETRIC: compute upper
// triangle of 32x32 block grid, mirror on store.
// BM=BN=32, BK=16, 128 threads, 2x4 per thread. grid (4,4,B), rt<=ct only.
// =====================================================================
__global__ void __launch_bounds__(128) ab_logits_kernel()
{
    const int b = blockIdx.z, ct = blockIdx.x, rt = blockIdx.y;
    if (rt > ct) return;
    const float* X = &g_fbq[b * NN * DD];
    const int r0 = rt * 32, c0 = ct * 32;

    __shared__ __align__(16) float As[16][36];
    __shared__ __align__(16) float Bs[16][36];
    const int tid = threadIdx.x;  // 128
    const int tx = tid & 7, ty = tid >> 3;   // 8 n-groups x 16 m-groups
    const int lr = tid >> 2, lk = (tid & 3) * 4;

    float acc[2][4] = {};

    for (int k0 = 0; k0 < DD; k0 += 16) {
        const float4 av = *(const float4*)&X[(r0 + lr) * DD + k0 + lk];
        As[lk + 0][lr] = av.x; As[lk + 1][lr] = av.y;
        As[lk + 2][lr] = av.z; As[lk + 3][lr] = av.w;
        const float4 bv = *(const float4*)&X[(c0 + lr) * DD + k0 + lk];
        Bs[lk + 0][lr] = bv.x; Bs[lk + 1][lr] = bv.y;
        Bs[lk + 2][lr] = bv.z; Bs[lk + 3][lr] = bv.w;
        __syncthreads();

#pragma unroll
        for (int k = 0; k < 16; k++) {
            const float2 a = *(const float2*)&As[k][ty * 2];
            const float4 v = *(const float4*)&Bs[k][tx * 4];
            acc[0][0] += a.x * v.x; acc[0][1] += a.x * v.y; acc[0][2] += a.x * v.z; acc[0][3] += a.x * v.w;
            acc[1][0] += a.y * v.x; acc[1][1] += a.y * v.y; acc[1][2] += a.y * v.z; acc[1][3] += a.y * v.w;
        }
        __syncthreads();
    }

    float* Sb = &g_S[b * NN * NN];
#pragma unroll
    for (int i = 0; i < 2; i++) {
        const int row = r0 + ty * 2 + i;
        float4 o;
        o.x = acc[i][0] * SCALE; o.y = acc[i][1] * SCALE;
        o.z = acc[i][2] * SCALE; o.w = acc[i][3] * SCALE;
        *(float4*)&Sb[row * NN + c0 + tx * 4] = o;
        if (rt != ct) {
            Sb[(c0 + tx * 4 + 0) * NN + row] = o.x;
            Sb[(c0 + tx * 4 + 1) * NN + row] = o.y;
            Sb[(c0 + tx * 4 + 2) * NN + row] = o.z;
            Sb[(c0 + tx * 4 + 3) * NN + row] = o.w;
        }
    }
}

// =====================================================================
// K4: row softmax, warp per row, no barriers. grid 64 blocks, 256 thr.
// =====================================================================
__global__ void __launch_bounds__(256) softmax_kernel()
{
    const int tid = threadIdx.x;
    const int row = blockIdx.x * 8 + (tid >> 5);
    const int lane = tid & 31;

    float4 v = *(const float4*)&g_S[row * NN + lane * 4];
    float m = fmaxf(fmaxf(v.x, v.y), fmaxf(v.z, v.w));
#pragma unroll
    for (int o = 16; o > 0; o >>= 1) m = fmaxf(m, __shfl_xor_sync(0xffffffffu, m, o));
    float4 e;
    e.x = __expf(v.x - m); e.y = __expf(v.y - m);
    e.z = __expf(v.z - m); e.w = __expf(v.w - m);
    float s = e.x + e.y + e.z + e.w;
#pragma unroll
    for (int o = 16; o > 0; o >>= 1) s += __shfl_xor_sync(0xffffffffu, s, o);
    const float inv = 1.f / s;
    e.x *= inv; e.y *= inv; e.z *= inv; e.w *= inv;
    *(float4*)&g_A[row * NN + lane * 4] = e;
}

// =====================================================================
// K5: f_bb = A_b @ f_b  (per batch 128x512x128)
// BM=32(n), BN=64(d), BK=16(m), 256 threads, 2x4 per thread. grid (8,4,B)
// =====================================================================
__global__ void __launch_bounds__(256) fbb_kernel(const float* __restrict__ f_b)
{
    const int b = blockIdx.z;
    const int n0 = blockIdx.y * 32;
    const int d0 = blockIdx.x * 64;

    __shared__ __align__(16) float As[16][36];   // [m][n]
    __shared__ __align__(16) float Bs[16][68];   // [m][d]
    const int tid = threadIdx.x;   // 256
    const int tx = tid & 15, ty = tid >> 4;

    float acc[2][4] = {};

    const int ln = tid >> 3, lk2 = (tid & 7) * 2;   // A loader: 32 rows x 16 m
    const int br = tid >> 4, bc = (tid & 15) * 4;   // B loader: 16 rows x 64 d

    for (int k0 = 0; k0 < NN; k0 += 16) {
        const float2 a2 = *(const float2*)&g_A[(b * NN + n0 + ln) * NN + k0 + lk2];
        As[lk2][ln] = a2.x; As[lk2 + 1][ln] = a2.y;
        const float4 b4 = *(const float4*)&f_b[(b * NN + k0 + br) * DD + d0 + bc];
        *(float4*)&Bs[br][bc] = b4;
        __syncthreads();

#pragma unroll
        for (int m = 0; m < 16; m++) {
            const float2 a = *(const float2*)&As[m][ty * 2];
            const float4 v = *(const float4*)&Bs[m][tx * 4];
            acc[0][0] += a.x * v.x; acc[0][1] += a.x * v.y; acc[0][2] += a.x * v.z; acc[0][3] += a.x * v.w;
            acc[1][0] += a.y * v.x; acc[1][1] += a.y * v.y; acc[1][2] += a.y * v.z; acc[1][3] += a.y * v.w;
        }
        __syncthreads();
    }

#pragma unroll
    for (int i = 0; i < 2; i++) {
        float4 o;
        o.x = acc[i][0]; o.y = acc[i][1]; o.z = acc[i][2]; o.w = acc[i][3];
        *(float4*)&g_fbb[(b * NN + n0 + ty * 2 + i) * DD + d0 + tx * 4] = o;
    }
}

// =====================================================================
// K6: streaming f_m reduction + residual + f_bb.  float4 everywhere.
// 256 threads: i split in two halves (even/odd), smem combine.
// =====================================================================
__global__ void __launch_bounds__(256) final_kernel(
    const float* __restrict__ f_b, const float* __restrict__ f_s,
    const float* __restrict__ f_m, float* __restrict__ out)
{
    const int j = blockIdx.x, b = blockIdx.y;
    __shared__ float acol[NN];
    __shared__ __align__(16) float4 part[128];
    const int tid = threadIdx.x;  // 256
    if (tid < NN) acol[tid] = g_A[(b * NN + tid) * NN + j];
    __syncthreads();

    const int p = tid >> 7;        // i parity
    const int q = tid & 127;
    const int d4 = q * 4;
    const float4 fs4 = *(const float4*)&f_s[b * DD + d4];

    float4 acc = make_float4(0.f, 0.f, 0.f, 0.f);
    const float* fm = f_m + ((size_t)(b * NN * NN) + j) * DD;

#pragma unroll 4
    for (int i = p; i < NN; i += 2) {
        const float a = acol[i];
        const float4 v = *(const float4*)&fm[(size_t)i * NN * DD + d4];
        acc.x += a * __fdividef(v.x, 1.f + __expf(-v.x * fs4.x));
        acc.y += a * __fdividef(v.y, 1.f + __expf(-v.y * fs4.y));
        acc.z += a * __fdividef(v.z, 1.f + __expf(-v.z * fs4.z));
        acc.w += a * __fdividef(v.w, 1.f + __expf(-v.w * fs4.w));
    }

    if (p == 1) part[q] = acc;
    __syncthreads();

    if (p == 0) {
        const float4 pa = part[q];
        const size_t o = (size_t)(b * NN + j) * DD;
        const float4 fb4  = *(const float4*)&f_b[o + d4];
        const float4 fbb4 = *(const float4*)&g_fbb[o + d4];
        float4 r;
        r.x = acc.x + pa.x + fb4.x + fbb4.x;
        r.y = acc.y + pa.y + fb4.y + fbb4.y;
        r.z = acc.z + pa.z + fb4.z + fbb4.z;
        r.w = acc.w + pa.w + fb4.w + fbb4.w;
        *(float4*)&out[o + d4] = r;
    }
}

// =====================================================================
extern "C" void kernel_launch(void* const* d_in, const int* in_sizes, int n_in,
                              void* d_out, int out_size)
{
    const float* f_b = (const float*)d_in[0];
    const float* f_w = (const float*)d_in[1];
    const float* f_s = (const float*)d_in[2];
    const float* f_m = (const float*)d_in[3];
    const float* Wq  = (const float*)d_in[4];
    const float* bq  = (const float*)d_in[5];
    const float* Wk  = (const float*)d_in[6];
    const float* bk  = (const float*)d_in[7];
    float* out = (float*)d_out;

    proj_kernel<<<dim3(16, 10), 256>>>(f_b, f_w, Wq, bq, Wk, bk);
    cross_attn_kernel<<<dim3(NN, BB), 256>>>(f_b, f_w, f_s);
    ab_logits_kernel<<<dim3(4, 4, BB), 128>>>();
    softmax_kernel<<<64, 256>>>();
    fbb_kernel<<<dim3(8, 4, BB), 256>>>(f_b);
    final_kernel<<<dim3(NN, BB), 256>>>(f_b, f_s, f_m, out);
}

// round 6
// speedup vs baseline: 1.3803x; 1.0597x over previous
#include <cuda_runtime.h>
#include <math.h>

#define BB 4
#define NN 128
#define LL 20
#define DD 512
#define SCALE 0.044194173824159216f  // 1/sqrt(512)

// -------- scratch (device globals; no allocation allowed) --------
__device__ float g_q[BB * NN * DD];       // q projection (bias included)
__device__ float g_k[BB * LL * DD];       // k projection (bias included)
__device__ float g_fbq[BB * NN * DD];     // gated boundary features
__device__ float g_S0[BB * NN * NN];      // A_b logit partial (k 0..255)
__device__ float g_S1[BB * NN * NN];      // A_b logit partial (k 256..511)
__device__ float g_A[BB * NN * NN];       // A_b (post-softmax, for final)
__device__ float g_fbb[BB * NN * DD];     // A_b @ f_b

// packed fp32x2 FMA (Blackwell FFMA2)
__device__ __forceinline__ float2 ffma2(float2 a, float2 b, float2 c) {
    float2 d;
    asm("fma.rn.f32x2 %0, %1, %2, %3;"
        : "=l"(reinterpret_cast<unsigned long long&>(d))
        : "l"(reinterpret_cast<unsigned long long&>(a)),
          "l"(reinterpret_cast<unsigned long long&>(b)),
          "l"(reinterpret_cast<unsigned long long&>(c)));
    return d;
}

// =====================================================================
// K1: fused projections  q = f_b@Wq^T+bq,  k = f_w@Wk^T+bk
// BM=64, BN=32, BK=8, 64 threads, thread tile 8m x 4n, FFMA2 over
// natural m-pairs (B scalar dup in regs).  1.5 B of LDS per MAC.
// grid (16 ntiles, 10 mtiles): mtile<8 -> q (512 rows), else k (80 rows)
// =====================================================================
__global__ void __launch_bounds__(64) proj_kernel(
    const float* __restrict__ Xq, const float* __restrict__ Xk,
    const float* __restrict__ Wq, const float* __restrict__ bq,
    const float* __restrict__ Wk, const float* __restrict__ bk)
{
    const int ntile = blockIdx.x, mtile = blockIdx.y;
    const float *X, *W, *bias;
    float* C;
    int Mrows, row0;
    if (mtile < 8) { X = Xq; W = Wq; bias = bq; C = g_q; Mrows = BB * NN; row0 = mtile * 64; }
    else           { X = Xk; W = Wk; bias = bk; C = g_k; Mrows = BB * LL; row0 = (mtile - 8) * 64; }
    const int n0 = ntile * 32;

    __shared__ __align__(16) float As[8][68];  // [k][m]
    __shared__ __align__(16) float Bs[8][36];  // [k][n]

    const int tid = threadIdx.x;        // 64
    const int tx = tid & 7;             // n-group: n = tx*4
    const int ty = tid >> 3;            // m-group: m = ty*8
    const int bn = tid >> 1;            // B loader n row
    const int bkk = (tid & 1) * 4;      // B loader k offset
    const bool avalid = (row0 + tid) < Mrows;

    float2 acc[4][4] = {};  // [m-pair][n]

    for (int k0 = 0; k0 < DD; k0 += 8) {
        float4 a0 = make_float4(0.f, 0.f, 0.f, 0.f), a1 = a0;
        if (avalid) {
            a0 = *(const float4*)&X[(row0 + tid) * DD + k0];
            a1 = *(const float4*)&X[(row0 + tid) * DD + k0 + 4];
        }
        As[0][tid] = a0.x; As[1][tid] = a0.y; As[2][tid] = a0.z; As[3][tid] = a0.w;
        As[4][tid] = a1.x; As[5][tid] = a1.y; As[6][tid] = a1.z; As[7][tid] = a1.w;
        const float4 wv = *(const float4*)&W[(n0 + bn) * DD + k0 + bkk];
        Bs[bkk + 0][bn] = wv.x; Bs[bkk + 1][bn] = wv.y;
        Bs[bkk + 2][bn] = wv.z; Bs[bkk + 3][bn] = wv.w;
        __syncthreads();

#pragma unroll
        for (int kk = 0; kk < 8; kk++) {
            const float4 am0 = *(const float4*)&As[kk][ty * 8];
            const float4 am1 = *(const float4*)&As[kk][ty * 8 + 4];
            const float4 bv  = *(const float4*)&Bs[kk][tx * 4];
            const float2 mp0 = make_float2(am0.x, am0.y);
            const float2 mp1 = make_float2(am0.z, am0.w);
            const float2 mp2 = make_float2(am1.x, am1.y);
            const float2 mp3 = make_float2(am1.z, am1.w);
            const float2 d0 = make_float2(bv.x, bv.x);
            const float2 d1 = make_float2(bv.y, bv.y);
            const float2 d2 = make_float2(bv.z, bv.z);
            const float2 d3 = make_float2(bv.w, bv.w);
            acc[0][0] = ffma2(mp0, d0, acc[0][0]); acc[0][1] = ffma2(mp0, d1, acc[0][1]);
            acc[0][2] = ffma2(mp0, d2, acc[0][2]); acc[0][3] = ffma2(mp0, d3, acc[0][3]);
            acc[1][0] = ffma2(mp1, d0, acc[1][0]); acc[1][1] = ffma2(mp1, d1, acc[1][1]);
            acc[1][2] = ffma2(mp1, d2, acc[1][2]); acc[1][3] = ffma2(mp1, d3, acc[1][3]);
            acc[2][0] = ffma2(mp2, d0, acc[2][0]); acc[2][1] = ffma2(mp2, d1, acc[2][1]);
            acc[2][2] = ffma2(mp2, d2, acc[2][2]); acc[2][3] = ffma2(mp2, d3, acc[2][3]);
            acc[3][0] = ffma2(mp3, d0, acc[3][0]); acc[3][1] = ffma2(mp3, d1, acc[3][1]);
            acc[3][2] = ffma2(mp3, d2, acc[3][2]); acc[3][3] = ffma2(mp3, d3, acc[3][3]);
        }
        __syncthreads();
    }

    const float4 bv4 = *(const float4*)&bias[n0 + tx * 4];
#pragma unroll
    for (int i = 0; i < 4; i++) {
        const int r0 = row0 + ty * 8 + 2 * i;
        if (r0 < Mrows) {
            float4 v;
            v.x = acc[i][0].x + bv4.x; v.y = acc[i][1].x + bv4.y;
            v.z = acc[i][2].x + bv4.z; v.w = acc[i][3].x + bv4.w;
            *(float4*)&C[r0 * DD + n0 + tx * 4] = v;
        }
        if (r0 + 1 < Mrows) {
            float4 v;
            v.x = acc[i][0].y + bv4.x; v.y = acc[i][1].y + bv4.y;
            v.z = acc[i][2].y + bv4.z; v.w = acc[i][3].y + bv4.w;
            *(float4*)&C[(r0 + 1) * DD + n0 + tx * 4] = v;
        }
    }
}

// =====================================================================
// K2: fused cross-attention + sentence gate.  One block per (b, n).
// =====================================================================
__global__ void __launch_bounds__(256) cross_attn_kernel(
    const float* __restrict__ f_b, const float* __restrict__ f_w,
    const float* __restrict__ f_s)
{
    const int n = blockIdx.x, b = blockIdx.y;
    __shared__ float qs[DD];
    __shared__ float logit[24];
    __shared__ float attn[24];
    const int tid = threadIdx.x;  // 256
    const int w = tid >> 5, lane = tid & 31;

    const float* qrow = &g_q[(b * NN + n) * DD];
    for (int d = tid; d < DD; d += 256) qs[d] = qrow[d];
    __syncthreads();

    for (int l = w; l < LL; l += 8) {
        const float* krow = &g_k[(b * LL + l) * DD];
        float s = 0.f;
        for (int d = lane; d < DD; d += 32) s += qs[d] * krow[d];
#pragma unroll
        for (int o = 16; o > 0; o >>= 1) s += __shfl_xor_sync(0xffffffffu, s, o);
        if (lane == 0) logit[l] = s * SCALE;
    }
    __syncthreads();

    if (tid < 32) {
        float lg = (tid < LL) ? logit[tid] : -1e30f;
        float mx = lg;
#pragma unroll
        for (int o = 16; o > 0; o >>= 1) mx = fmaxf(mx, __shfl_xor_sync(0xffffffffu, mx, o));
        float e = (tid < LL) ? __expf(lg - mx) : 0.f;
        float s = e;
#pragma unroll
        for (int o = 16; o > 0; o >>= 1) s += __shfl_xor_sync(0xffffffffu, s, o);
        if (tid < LL) attn[tid] = e / s;
    }
    __syncthreads();

    for (int d = tid; d < DD; d += 256) {
        float acc = 0.f;
#pragma unroll
        for (int l = 0; l < LL; l++) acc += attn[l] * f_w[(b * LL + l) * DD + d];
        const float v = f_b[(b * NN + n) * DD + d] * (acc + f_s[b * DD + d]);
        g_fbq[(b * NN + n) * DD + d] = v;
    }
}

// =====================================================================
// K3: A_b logit partials = scale * f_bq @ f_bq^T.  SYMMETRIC (rt<=ct)
// + K-SPLIT x2 (kz halves of D into g_S0 / g_S1, summed in K4).
// 32x32 tile, 64 threads, 4x4 per thread. grid (4 ct, 4 rt, 8 = b*2+kz)
// =====================================================================
__global__ void __launch_bounds__(64) ab_logits_kernel()
{
    const int ct = blockIdx.x, rt = blockIdx.y;
    if (rt > ct) return;
    const int b = blockIdx.z >> 1, kz = blockIdx.z & 1;
    const float* X = &g_fbq[b * NN * DD];
    float* Sb = (kz == 0) ? &g_S0[b * NN * NN] : &g_S1[b * NN * NN];
    const int r0 = rt * 32, c0 = ct * 32;
    const int kbeg = kz * 256, kend = kbeg + 256;

    __shared__ __align__(16) float As[16][36];
    __shared__ __align__(16) float Bs[16][36];
    const int tid = threadIdx.x;  // 64
    const int tx = tid & 7, ty = tid >> 3;   // n = tx*4, m = ty*4
    const int lr = tid >> 1, lk = (tid & 1) * 8;

    float acc[4][4] = {};

    for (int k0 = kbeg; k0 < kend; k0 += 16) {
        const float4 a0 = *(const float4*)&X[(r0 + lr) * DD + k0 + lk];
        const float4 a1 = *(const float4*)&X[(r0 + lr) * DD + k0 + lk + 4];
        As[lk + 0][lr] = a0.x; As[lk + 1][lr] = a0.y; As[lk + 2][lr] = a0.z; As[lk + 3][lr] = a0.w;
        As[lk + 4][lr] = a1.x; As[lk + 5][lr] = a1.y; As[lk + 6][lr] = a1.z; As[lk + 7][lr] = a1.w;
        const float4 b0 = *(const float4*)&X[(c0 + lr) * DD + k0 + lk];
        const float4 b1 = *(const float4*)&X[(c0 + lr) * DD + k0 + lk + 4];
        Bs[lk + 0][lr] = b0.x; Bs[lk + 1][lr] = b0.y; Bs[lk + 2][lr] = b0.z; Bs[lk + 3][lr] = b0.w;
        Bs[lk + 4][lr] = b1.x; Bs[lk + 5][lr] = b1.y; Bs[lk + 6][lr] = b1.z; Bs[lk + 7][lr] = b1.w;
        __syncthreads();

#pragma unroll
        for (int k = 0; k < 16; k++) {
            const float4 a = *(const float4*)&As[k][ty * 4];
            const float4 v = *(const float4*)&Bs[k][tx * 4];
            acc[0][0] += a.x * v.x; acc[0][1] += a.x * v.y; acc[0][2] += a.x * v.z; acc[0][3] += a.x * v.w;
            acc[1][0] += a.y * v.x; acc[1][1] += a.y * v.y; acc[1][2] += a.y * v.z; acc[1][3] += a.y * v.w;
            acc[2][0] += a.z * v.x; acc[2][1] += a.z * v.y; acc[2][2] += a.z * v.z; acc[2][3] += a.z * v.w;
            acc[3][0] += a.w * v.x; acc[3][1] += a.w * v.y; acc[3][2] += a.w * v.z; acc[3][3] += a.w * v.w;
        }
        __syncthreads();
    }

#pragma unroll
    for (int i = 0; i < 4; i++) {
        const int row = r0 + ty * 4 + i;
        float4 o;
        o.x = acc[i][0] * SCALE; o.y = acc[i][1] * SCALE;
        o.z = acc[i][2] * SCALE; o.w = acc[i][3] * SCALE;
        *(float4*)&Sb[row * NN + c0 + tx * 4] = o;
        if (rt != ct) {
            Sb[(c0 + tx * 4 + 0) * NN + row] = o.x;
            Sb[(c0 + tx * 4 + 1) * NN + row] = o.y;
            Sb[(c0 + tx * 4 + 2) * NN + row] = o.z;
            Sb[(c0 + tx * 4 + 3) * NN + row] = o.w;
        }
    }
}

// =====================================================================
// K4: fused softmax + f_bb = A_b @ f_b.
// Phase 1: softmax rows n0..n0+31 of (S0+S1) into smem Asm[m][n]
//          (d-tile 0 also writes g_A for K5).
// Phase 2: GEMM  f_bb[n, d0..d0+63] = sum_m Asm[m][n] * f_b[m][d]
// 256 threads, grid (8 d-tiles, 4 n-tiles, B)
// =====================================================================
__global__ void __launch_bounds__(256) fbb_softmax_kernel(const float* __restrict__ f_b)
{
    const int dx = blockIdx.x, nt = blockIdx.y, b = blockIdx.z;
    const int n0 = nt * 32, d0 = dx * 64;

    __shared__ float Asm[NN][33];                // [m][n-local] softmax'd A^T
    __shared__ __align__(16) float Bs[16][68];   // [m][d]
    const int tid = threadIdx.x;  // 256
    const int w = tid >> 5, lane = tid & 31;

    // ---- phase 1: softmax 32 rows (4 per warp) ----
#pragma unroll
    for (int i = 0; i < 4; i++) {
        const int row = w + i * 8;                  // local n
        const int grow = (b * NN + n0 + row) * NN;
        const float4 s0 = *(const float4*)&g_S0[grow + lane * 4];
        const float4 s1 = *(const float4*)&g_S1[grow + lane * 4];
        float4 v;
        v.x = s0.x + s1.x; v.y = s0.y + s1.y; v.z = s0.z + s1.z; v.w = s0.w + s1.w;
        float m = fmaxf(fmaxf(v.x, v.y), fmaxf(v.z, v.w));
#pragma unroll
        for (int o = 16; o > 0; o >>= 1) m = fmaxf(m, __shfl_xor_sync(0xffffffffu, m, o));
        float4 e;
        e.x = __expf(v.x - m); e.y = __expf(v.y - m);
        e.z = __expf(v.z - m); e.w = __expf(v.w - m);
        float s = e.x + e.y + e.z + e.w;
#pragma unroll
        for (int o = 16; o > 0; o >>= 1) s += __shfl_xor_sync(0xffffffffu, s, o);
        const float inv = 1.f / s;
        e.x *= inv; e.y *= inv; e.z *= inv; e.w *= inv;
        Asm[lane * 4 + 0][row] = e.x;
        Asm[lane * 4 + 1][row] = e.y;
        Asm[lane * 4 + 2][row] = e.z;
        Asm[lane * 4 + 3][row] = e.w;
        if (dx == 0) *(float4*)&g_A[grow + lane * 4] = e;
    }
    __syncthreads();

    // ---- phase 2: GEMM from smem A ----
    const int tx = tid & 15, ty = tid >> 4;         // d = tx*4, n-pair = ty*2
    const int br = tid >> 4, bc = (tid & 15) * 4;   // B loader

    float acc[2][4] = {};

    for (int m0 = 0; m0 < NN; m0 += 16) {
        const float4 b4 = *(const float4*)&f_b[(b * NN + m0 + br) * DD + d0 + bc];
        *(float4*)&Bs[br][bc] = b4;
        __syncthreads();

#pragma unroll
        for (int mm = 0; mm < 16; mm++) {
            const float a0 = Asm[m0 + mm][ty * 2];
            const float a1 = Asm[m0 + mm][ty * 2 + 1];
            const float4 v = *(const float4*)&Bs[mm][tx * 4];
            acc[0][0] += a0 * v.x; acc[0][1] += a0 * v.y; acc[0][2] += a0 * v.z; acc[0][3] += a0 * v.w;
            acc[1][0] += a1 * v.x; acc[1][1] += a1 * v.y; acc[1][2] += a1 * v.z; acc[1][3] += a1 * v.w;
        }
        __syncthreads();
    }

#pragma unroll
    for (int i = 0; i < 2; i++) {
        float4 o;
        o.x = acc[i][0]; o.y = acc[i][1]; o.z = acc[i][2]; o.w = acc[i][3];
        *(float4*)&g_fbb[(b * NN + n0 + ty * 2 + i) * DD + d0 + tx * 4] = o;
    }
}

// =====================================================================
// K5: streaming f_m reduction + residual + f_bb.  float4, i-split x2.
// =====================================================================
__global__ void __launch_bounds__(256) final_kernel(
    const float* __restrict__ f_b, const float* __restrict__ f_s,
    const float* __restrict__ f_m, float* __restrict__ out)
{
    const int j = blockIdx.x, b = blockIdx.y;
    __shared__ float acol[NN];
    __shared__ __align__(16) float4 part[128];
    const int tid = threadIdx.x;  // 256
    if (tid < NN) acol[tid] = g_A[(b * NN + tid) * NN + j];
    __syncthreads();

    const int p = tid >> 7;        // i parity
    const int q = tid & 127;
    const int d4 = q * 4;
    const float4 fs4 = *(const float4*)&f_s[b * DD + d4];

    float4 acc = make_float4(0.f, 0.f, 0.f, 0.f);
    const float* fm = f_m + ((size_t)(b * NN * NN) + j) * DD;

#pragma unroll 4
    for (int i = p; i < NN; i += 2) {
        const float a = acol[i];
        const float4 v = *(const float4*)&fm[(size_t)i * NN * DD + d4];
        acc.x += a * __fdividef(v.x, 1.f + __expf(-v.x * fs4.x));
        acc.y += a * __fdividef(v.y, 1.f + __expf(-v.y * fs4.y));
        acc.z += a * __fdividef(v.z, 1.f + __expf(-v.z * fs4.z));
        acc.w += a * __fdividef(v.w, 1.f + __expf(-v.w * fs4.w));
    }

    if (p == 1) part[q] = acc;
    __syncthreads();

    if (p == 0) {
        const float4 pa = part[q];
        const size_t o = (size_t)(b * NN + j) * DD;
        const float4 fb4  = *(const float4*)&f_b[o + d4];
        const float4 fbb4 = *(const float4*)&g_fbb[o + d4];
        float4 r;
        r.x = acc.x + pa.x + fb4.x + fbb4.x;
        r.y = acc.y + pa.y + fb4.y + fbb4.y;
        r.z = acc.z + pa.z + fb4.z + fbb4.z;
        r.w = acc.w + pa.w + fb4.w + fbb4.w;
        *(float4*)&out[o + d4] = r;
    }
}

// =====================================================================
extern "C" void kernel_launch(void* const* d_in, const int* in_sizes, int n_in,
                              void* d_out, int out_size)
{
    const float* f_b = (const float*)d_in[0];
    const float* f_w = (const float*)d_in[1];
    const float* f_s = (const float*)d_in[2];
    const float* f_m = (const float*)d_in[3];
    const float* Wq  = (const float*)d_in[4];
    const float* bq  = (const float*)d_in[5];
    const float* Wk  = (const float*)d_in[6];
    const float* bk  = (const float*)d_in[7];
    float* out = (float*)d_out;

    proj_kernel<<<dim3(16, 10), 64>>>(f_b, f_w, Wq, bq, Wk, bk);
    cross_attn_kernel<<<dim3(NN, BB), 256>>>(f_b, f_w, f_s);
    ab_logits_kernel<<<dim3(4, 4, BB * 2), 64>>>();
    fbb_softmax_kernel<<<dim3(8, 4, BB), 256>>>(f_b);
    final_kernel<<<dim3(NN, BB), 256>>>(f_b, f_s, f_m, out);
}

// round 8
// speedup vs baseline: 1.5479x; 1.1215x over previous
#include <cuda_runtime.h>
#include <math.h>

#define BB 4
#define NN 128
#define LL 20
#define DD 512
#define SCALE 0.044194173824159216f  // 1/sqrt(512)

// -------- scratch (device globals; no allocation allowed) --------
__device__ float g_q[BB * NN * DD];       // q projection (bias included)
__device__ float g_k[BB * LL * DD];       // k projection (bias included)
__device__ float g_fbq[BB * NN * DD];     // gated boundary features
__device__ float g_S0[BB * NN * NN];      // A_b logit partial (k 0..255)
__device__ float g_S1[BB * NN * NN];      // A_b logit partial (k 256..511)
__device__ float g_A[BB * NN * NN];       // A_b rows   (A[b][i][j])
__device__ float g_At[BB * NN * NN];      // A_b transposed (At[b][j][i])

// packed fp32x2 FMA (Blackwell FFMA2)
__device__ __forceinline__ float2 ffma2(float2 a, float2 b, float2 c) {
    float2 d;
    asm("fma.rn.f32x2 %0, %1, %2, %3;"
        : "=l"(reinterpret_cast<unsigned long long&>(d))
        : "l"(reinterpret_cast<unsigned long long&>(a)),
          "l"(reinterpret_cast<unsigned long long&>(b)),
          "l"(reinterpret_cast<unsigned long long&>(c)));
    return d;
}

// =====================================================================
// K1: fused projections  q = f_b@Wq^T+bq,  k = f_w@Wk^T+bk
// BM=64, BN=32, BK=16, 128 threads, double-buffered smem + reg prefetch.
// Thread tile 4m x 4n via FFMA2 m-pairs.  grid (16 ntiles, 10 mtiles).
// =====================================================================
__global__ void __launch_bounds__(128) proj_kernel(
    const float* __restrict__ Xq, const float* __restrict__ Xk,
    const float* __restrict__ Wq, const float* __restrict__ bq,
    const float* __restrict__ Wk, const float* __restrict__ bk)
{
    const int ntile = blockIdx.x, mtile = blockIdx.y;
    const float *X, *W, *bias;
    float* C;
    int Mrows, row0;
    if (mtile < 8) { X = Xq; W = Wq; bias = bq; C = g_q; Mrows = BB * NN; row0 = mtile * 64; }
    else           { X = Xk; W = Wk; bias = bk; C = g_k; Mrows = BB * LL; row0 = (mtile - 8) * 64; }
    const int n0 = ntile * 32;

    __shared__ __align__(16) float As[2][16][68];  // [buf][k][m]
    __shared__ __align__(16) float Bs[2][16][36];  // [buf][k][n]

    const int tid = threadIdx.x;        // 128
    const int tx = tid & 7;             // n = tx*4
    const int ty = tid >> 3;            // m = ty*4 (0..15)
    const int ar = tid >> 1;            // A loader row 0..63
    const int ak = (tid & 1) * 8;       // A loader k offset (2 float4)
    const int bn = tid >> 2;            // B loader n row 0..31
    const int bkk = (tid & 3) * 4;      // B loader k offset
    const bool avalid = (row0 + ar) < Mrows;

    float2 acc[2][4] = {};  // [m-pair][n]

    // prologue: load tile 0
    float4 pa0 = make_float4(0.f, 0.f, 0.f, 0.f), pa1 = pa0, pb;
    if (avalid) {
        pa0 = *(const float4*)&X[(row0 + ar) * DD + ak];
        pa1 = *(const float4*)&X[(row0 + ar) * DD + ak + 4];
    }
    pb = *(const float4*)&W[(n0 + bn) * DD + bkk];
    As[0][ak + 0][ar] = pa0.x; As[0][ak + 1][ar] = pa0.y; As[0][ak + 2][ar] = pa0.z; As[0][ak + 3][ar] = pa0.w;
    As[0][ak + 4][ar] = pa1.x; As[0][ak + 5][ar] = pa1.y; As[0][ak + 6][ar] = pa1.z; As[0][ak + 7][ar] = pa1.w;
    Bs[0][bkk + 0][bn] = pb.x; Bs[0][bkk + 1][bn] = pb.y; Bs[0][bkk + 2][bn] = pb.z; Bs[0][bkk + 3][bn] = pb.w;
    __syncthreads();

    for (int t = 0; t < 32; t++) {
        const int cur = t & 1;
        if (t < 31) {
            const int k0 = (t + 1) * 16;
            pa0 = make_float4(0.f, 0.f, 0.f, 0.f); pa1 = pa0;
            if (avalid) {
                pa0 = *(const float4*)&X[(row0 + ar) * DD + k0 + ak];
                pa1 = *(const float4*)&X[(row0 + ar) * DD + k0 + ak + 4];
            }
            pb = *(const float4*)&W[(n0 + bn) * DD + k0 + bkk];
        }

#pragma unroll
        for (int kk = 0; kk < 16; kk++) {
            const float4 a = *(const float4*)&As[cur][kk][ty * 4];
            const float4 bv = *(const float4*)&Bs[cur][kk][tx * 4];
            const float2 mp0 = make_float2(a.x, a.y);
            const float2 mp1 = make_float2(a.z, a.w);
            const float2 d0 = make_float2(bv.x, bv.x);
            const float2 d1 = make_float2(bv.y, bv.y);
            const float2 d2 = make_float2(bv.z, bv.z);
            const float2 d3 = make_float2(bv.w, bv.w);
            acc[0][0] = ffma2(mp0, d0, acc[0][0]); acc[0][1] = ffma2(mp0, d1, acc[0][1]);
            acc[0][2] = ffma2(mp0, d2, acc[0][2]); acc[0][3] = ffma2(mp0, d3, acc[0][3]);
            acc[1][0] = ffma2(mp1, d0, acc[1][0]); acc[1][1] = ffma2(mp1, d1, acc[1][1]);
            acc[1][2] = ffma2(mp1, d2, acc[1][2]); acc[1][3] = ffma2(mp1, d3, acc[1][3]);
        }
        __syncthreads();

        if (t < 31) {
            const int nxt = cur ^ 1;
            As[nxt][ak + 0][ar] = pa0.x; As[nxt][ak + 1][ar] = pa0.y;
            As[nxt][ak + 2][ar] = pa0.z; As[nxt][ak + 3][ar] = pa0.w;
            As[nxt][ak + 4][ar] = pa1.x; As[nxt][ak + 5][ar] = pa1.y;
            As[nxt][ak + 6][ar] = pa1.z; As[nxt][ak + 7][ar] = pa1.w;
            Bs[nxt][bkk + 0][bn] = pb.x; Bs[nxt][bkk + 1][bn] = pb.y;
            Bs[nxt][bkk + 2][bn] = pb.z; Bs[nxt][bkk + 3][bn] = pb.w;
            __syncthreads();
        }
    }

    const float4 bv4 = *(const float4*)&bias[n0 + tx * 4];
#pragma unroll
    for (int mp = 0; mp < 2; mp++) {
        const int r0 = row0 + ty * 4 + 2 * mp;
        if (r0 < Mrows) {
            float4 v;
            v.x = acc[mp][0].x + bv4.x; v.y = acc[mp][1].x + bv4.y;
            v.z = acc[mp][2].x + bv4.z; v.w = acc[mp][3].x + bv4.w;
            *(float4*)&C[r0 * DD + n0 + tx * 4] = v;
        }
        if (r0 + 1 < Mrows) {
            float4 v;
            v.x = acc[mp][0].y + bv4.x; v.y = acc[mp][1].y + bv4.y;
            v.z = acc[mp][2].y + bv4.z; v.w = acc[mp][3].y + bv4.w;
            *(float4*)&C[(r0 + 1) * DD + n0 + tx * 4] = v;
        }
    }
}

// =====================================================================
// K2: fused cross-attention + sentence gate.  One block per (b, n).
// =====================================================================
__global__ void __launch_bounds__(256) cross_attn_kernel(
    const float* __restrict__ f_b, const float* __restrict__ f_w,
    const float* __restrict__ f_s)
{
    const int n = blockIdx.x, b = blockIdx.y;
    __shared__ float qs[DD];
    __shared__ float logit[24];
    __shared__ float attn[24];
    const int tid = threadIdx.x;  // 256
    const int w = tid >> 5, lane = tid & 31;

    const float* qrow = &g_q[(b * NN + n) * DD];
    for (int d = tid; d < DD; d += 256) qs[d] = qrow[d];
    __syncthreads();

    for (int l = w; l < LL; l += 8) {
        const float* krow = &g_k[(b * LL + l) * DD];
        float s = 0.f;
        for (int d = lane; d < DD; d += 32) s += qs[d] * krow[d];
#pragma unroll
        for (int o = 16; o > 0; o >>= 1) s += __shfl_xor_sync(0xffffffffu, s, o);
        if (lane == 0) logit[l] = s * SCALE;
    }
    __syncthreads();

    if (tid < 32) {
        float lg = (tid < LL) ? logit[tid] : -1e30f;
        float mx = lg;
#pragma unroll
        for (int o = 16; o > 0; o >>= 1) mx = fmaxf(mx, __shfl_xor_sync(0xffffffffu, mx, o));
        float e = (tid < LL) ? __expf(lg - mx) : 0.f;
        float s = e;
#pragma unroll
        for (int o = 16; o > 0; o >>= 1) s += __shfl_xor_sync(0xffffffffu, s, o);
        if (tid < LL) attn[tid] = e / s;
    }
    __syncthreads();

    for (int d = tid; d < DD; d += 256) {
        float acc = 0.f;
#pragma unroll
        for (int l = 0; l < LL; l++) acc += attn[l] * f_w[(b * LL + l) * DD + d];
        const float v = f_b[(b * NN + n) * DD + d] * (acc + f_s[b * DD + d]);
        g_fbq[(b * NN + n) * DD + d] = v;
    }
}

// =====================================================================
// K3: A_b logit partials = scale * f_bq @ f_bq^T.  SYMMETRIC (rt<=ct),
// K-SPLIT x2, 128 threads, double-buffered, FFMA2.
// grid (4 ct, 4 rt, 8 = b*2+kz)
// =====================================================================
__global__ void __launch_bounds__(128) ab_logits_kernel()
{
    const int ct = blockIdx.x, rt = blockIdx.y;
    if (rt > ct) return;
    const int b = blockIdx.z >> 1, kz = blockIdx.z & 1;
    const float* X = &g_fbq[b * NN * DD];
    float* Sb = (kz == 0) ? &g_S0[b * NN * NN] : &g_S1[b * NN * NN];
    const int r0 = rt * 32, c0 = ct * 32;
    const int kbeg = kz * 256;

    __shared__ __align__(16) float As[2][16][36];
    __shared__ __align__(16) float Bs[2][16][36];
    const int tid = threadIdx.x;  // 128
    const int tx = tid & 7;       // n = tx*4
    const int ty = tid >> 3;      // m-pair base: m = ty*2 (0..15)
    const int lr = tid >> 2;      // loader row 0..31
    const int lk = (tid & 3) * 4; // loader k offset

    float2 acc[4] = {};  // [n], m-pair in .x/.y

    float4 pa = *(const float4*)&X[(r0 + lr) * DD + kbeg + lk];
    float4 pbv = *(const float4*)&X[(c0 + lr) * DD + kbeg + lk];
    As[0][lk + 0][lr] = pa.x; As[0][lk + 1][lr] = pa.y; As[0][lk + 2][lr] = pa.z; As[0][lk + 3][lr] = pa.w;
    Bs[0][lk + 0][lr] = pbv.x; Bs[0][lk + 1][lr] = pbv.y; Bs[0][lk + 2][lr] = pbv.z; Bs[0][lk + 3][lr] = pbv.w;
    __syncthreads();

    for (int t = 0; t < 16; t++) {
        const int cur = t & 1;
        if (t < 15) {
            const int k0 = kbeg + (t + 1) * 16;
            pa = *(const float4*)&X[(r0 + lr) * DD + k0 + lk];
            pbv = *(const float4*)&X[(c0 + lr) * DD + k0 + lk];
        }

#pragma unroll
        for (int kk = 0; kk < 16; kk++) {
            const float2 a = *(const float2*)&As[cur][kk][ty * 2];
            const float4 bv = *(const float4*)&Bs[cur][kk][tx * 4];
            acc[0] = ffma2(a, make_float2(bv.x, bv.x), acc[0]);
            acc[1] = ffma2(a, make_float2(bv.y, bv.y), acc[1]);
            acc[2] = ffma2(a, make_float2(bv.z, bv.z), acc[2]);
            acc[3] = ffma2(a, make_float2(bv.w, bv.w), acc[3]);
        }
        __syncthreads();

        if (t < 15) {
            const int nxt = cur ^ 1;
            As[nxt][lk + 0][lr] = pa.x; As[nxt][lk + 1][lr] = pa.y;
            As[nxt][lk + 2][lr] = pa.z; As[nxt][lk + 3][lr] = pa.w;
            Bs[nxt][lk + 0][lr] = pbv.x; Bs[nxt][lk + 1][lr] = pbv.y;
            Bs[nxt][lk + 2][lr] = pbv.z; Bs[nxt][lk + 3][lr] = pbv.w;
            __syncthreads();
        }
    }

#pragma unroll
    for (int h = 0; h < 2; h++) {
        const int row = r0 + ty * 2 + h;
        float4 o;
        o.x = (h ? acc[0].y : acc[0].x) * SCALE;
        o.y = (h ? acc[1].y : acc[1].x) * SCALE;
        o.z = (h ? acc[2].y : acc[2].x) * SCALE;
        o.w = (h ? acc[3].y : acc[3].x) * SCALE;
        *(float4*)&Sb[row * NN + c0 + tx * 4] = o;
        if (rt != ct) {
            Sb[(c0 + tx * 4 + 0) * NN + row] = o.x;
            Sb[(c0 + tx * 4 + 1) * NN + row] = o.y;
            Sb[(c0 + tx * 4 + 2) * NN + row] = o.z;
            Sb[(c0 + tx * 4 + 3) * NN + row] = o.w;
        }
    }
}

// =====================================================================
// K4: softmax of (S0+S1): writes g_A (row-major) AND g_At (transposed,
// for coalesced column access in K5).  Warp per row; 128 blocks x 128.
// =====================================================================
__global__ void __launch_bounds__(128) softmax_kernel()
{
    const int w = threadIdx.x >> 5, lane = threadIdx.x & 31;
    const int r = blockIdx.x * 4 + w;        // global row 0..511
    const int b = r >> 7, j = r & 127;

    const float4 s0 = *(const float4*)&g_S0[r * NN + lane * 4];
    const float4 s1 = *(const float4*)&g_S1[r * NN + lane * 4];
    float4 v;
    v.x = s0.x + s1.x; v.y = s0.y + s1.y; v.z = s0.z + s1.z; v.w = s0.w + s1.w;

    float m = fmaxf(fmaxf(v.x, v.y), fmaxf(v.z, v.w));
#pragma unroll
    for (int o = 16; o > 0; o >>= 1) m = fmaxf(m, __shfl_xor_sync(0xffffffffu, m, o));
    float4 e;
    e.x = __expf(v.x - m); e.y = __expf(v.y - m);
    e.z = __expf(v.z - m); e.w = __expf(v.w - m);
    float s = e.x + e.y + e.z + e.w;
#pragma unroll
    for (int o = 16; o > 0; o >>= 1) s += __shfl_xor_sync(0xffffffffu, s, o);
    const float inv = 1.f / s;
    e.x *= inv; e.y *= inv; e.z *= inv; e.w *= inv;

    *(float4*)&g_A[r * NN + lane * 4] = e;
    float* At = &g_At[b * NN * NN];
    At[(lane * 4 + 0) * NN + j] = e.x;
    At[(lane * 4 + 1) * NN + j] = e.y;
    At[(lane * 4 + 2) * NN + j] = e.z;
    At[(lane * 4 + 3) * NN + j] = e.w;
}

// =====================================================================
// K5: fused final:  out[b,j,:] = f_b + (A_b @ f_b)[j] + f_bm[j]
//   f_bb inline: sum_m A[j,m]*f_b[m,:]  (m-range split across p halves)
//   f_bm stream: sum_i A[i,j]*sigmoid(fm*fs)*fm  (i-parity split)
// 256 threads, block (j, b).
// =====================================================================
__global__ void __launch_bounds__(256) final_kernel(
    const float* __restrict__ f_b, const float* __restrict__ f_s,
    const float* __restrict__ f_m, float* __restrict__ out)
{
    const int j = blockIdx.x, b = blockIdx.y;
    __shared__ float arow[NN];   // A[b][j][:]
    __shared__ float acol[NN];   // A[b][:][j]
    __shared__ __align__(16) float4 part[128];
    const int tid = threadIdx.x;  // 256
    if (tid < NN) arow[tid] = g_A[(b * NN + j) * NN + tid];
    else          acol[tid - NN] = g_At[b * NN * NN + j * NN + (tid - NN)];
    __syncthreads();

    const int p = tid >> 7;
    const int q = tid & 127;
    const int d4 = q * 4;
    const float4 fs4 = *(const float4*)&f_s[b * DD + d4];

    float4 acc = make_float4(0.f, 0.f, 0.f, 0.f);

    // ---- f_bb partial: m in [p*64, p*64+64), L2-resident f_b ----
    const float* fbb_base = f_b + (size_t)b * NN * DD;
#pragma unroll 4
    for (int m = p * 64; m < p * 64 + 64; m++) {
        const float a = arow[m];
        const float4 v = *(const float4*)&fbb_base[(size_t)m * DD + d4];
        acc.x += a * v.x; acc.y += a * v.y; acc.z += a * v.z; acc.w += a * v.w;
    }

    // ---- f_bm partial: i = p, p+2, ... (DRAM stream) ----
    const float* fm = f_m + ((size_t)(b * NN * NN) + j) * DD;
#pragma unroll 4
    for (int i = p; i < NN; i += 2) {
        const float a = acol[i];
        const float4 v = *(const float4*)&fm[(size_t)i * NN * DD + d4];
        acc.x += a * __fdividef(v.x, 1.f + __expf(-v.x * fs4.x));
        acc.y += a * __fdividef(v.y, 1.f + __expf(-v.y * fs4.y));
        acc.z += a * __fdividef(v.z, 1.f + __expf(-v.z * fs4.z));
        acc.w += a * __fdividef(v.w, 1.f + __expf(-v.w * fs4.w));
    }

    if (p == 1) part[q] = acc;
    __syncthreads();

    if (p == 0) {
        const float4 pa = part[q];
        const size_t o = (size_t)(b * NN + j) * DD;
        const float4 fb4 = *(const float4*)&f_b[o + d4];
        float4 r;
        r.x = acc.x + pa.x + fb4.x;
        r.y = acc.y + pa.y + fb4.y;
        r.z = acc.z + pa.z + fb4.z;
        r.w = acc.w + pa.w + fb4.w;
        *(float4*)&out[o + d4] = r;
    }
}

// =====================================================================
extern "C" void kernel_launch(void* const* d_in, const int* in_sizes, int n_in,
                              void* d_out, int out_size)
{
    const float* f_b = (const float*)d_in[0];
    const float* f_w = (const float*)d_in[1];
    const float* f_s = (const float*)d_in[2];
    const float* f_m = (const float*)d_in[3];
    const float* Wq  = (const float*)d_in[4];
    const float* bq  = (const float*)d_in[5];
    const float* Wk  = (const float*)d_in[6];
    const float* bk  = (const float*)d_in[7];
    float* out = (float*)d_out;

    proj_kernel<<<dim3(16, 10), 128>>>(f_b, f_w, Wq, bq, Wk, bk);
    cross_attn_kernel<<<dim3(NN, BB), 256>>>(f_b, f_w, f_s);
    ab_logits_kernel<<<dim3(4, 4, BB * 2), 128>>>();
    softmax_kernel<<<128, 128>>>();
    final_kernel<<<dim3(NN, BB), 256>>>(f_b, f_s, f_m, out);
}

// round 13
// speedup vs baseline: 1.9937x; 1.2879x over previous
#include <cuda_runtime.h>
#include <math.h>

#define BB 4
#define NN 128
#define LL 20
#define DD 512
#define SCALE 0.044194173824159216f  // 1/sqrt(512)

// -------- scratch (device globals; no allocation allowed) --------
__device__ float g_q[BB * NN * DD];       // q projection (bias included)
__device__ float g_k[BB * LL * DD];       // k projection (bias included)
__device__ float g_fbq[BB * NN * DD];     // gated boundary features
__device__ float g_S0[BB * NN * NN];      // A_b logit partial (k 0..255)
__device__ float g_S1[BB * NN * NN];      // A_b logit partial (k 256..511)
__device__ float g_A[BB * NN * NN];       // A_b rows   (A[b][i][j])
__device__ float g_At[BB * NN * NN];      // A_b transposed (At[b][j][i])

// packed fp32x2 FMA (Blackwell FFMA2)
__device__ __forceinline__ float2 ffma2(float2 a, float2 b, float2 c) {
    float2 d;
    asm("fma.rn.f32x2 %0, %1, %2, %3;"
        : "=l"(reinterpret_cast<unsigned long long&>(d))
        : "l"(reinterpret_cast<unsigned long long&>(a)),
          "l"(reinterpret_cast<unsigned long long&>(b)),
          "l"(reinterpret_cast<unsigned long long&>(c)));
    return d;
}

// MUFU.TANH fast tanh
__device__ __forceinline__ float fast_tanh(float x) {
    float t;
    asm("tanh.approx.f32 %0, %1;" : "=f"(t) : "f"(x));
    return t;
}

// =====================================================================
// K1: fused projections  q = f_b@Wq^T+bq,  k = f_w@Wk^T+bk
// BM=64, BN=32, BK=16, 128 threads, double-buffered smem + reg prefetch.
// =====================================================================
__global__ void __launch_bounds__(128) proj_kernel(
    const float* __restrict__ Xq, const float* __restrict__ Xk,
    const float* __restrict__ Wq, const float* __restrict__ bq,
    const float* __restrict__ Wk, const float* __restrict__ bk)
{
    const int ntile = blockIdx.x, mtile = blockIdx.y;
    const float *X, *W, *bias;
    float* C;
    int Mrows, row0;
    if (mtile < 8) { X = Xq; W = Wq; bias = bq; C = g_q; Mrows = BB * NN; row0 = mtile * 64; }
    else           { X = Xk; W = Wk; bias = bk; C = g_k; Mrows = BB * LL; row0 = (mtile - 8) * 64; }
    const int n0 = ntile * 32;

    __shared__ __align__(16) float As[2][16][68];  // [buf][k][m]
    __shared__ __align__(16) float Bs[2][16][36];  // [buf][k][n]

    const int tid = threadIdx.x;        // 128
    const int tx = tid & 7;             // n = tx*4
    const int ty = tid >> 3;            // m = ty*4 (0..15)
    const int ar = tid >> 1;            // A loader row 0..63
    const int ak = (tid & 1) * 8;       // A loader k offset (2 float4)
    const int bn = tid >> 2;            // B loader n row 0..31
    const int bkk = (tid & 3) * 4;      // B loader k offset
    const bool avalid = (row0 + ar) < Mrows;

    float2 acc[2][4] = {};  // [m-pair][n]

    float4 pa0 = make_float4(0.f, 0.f, 0.f, 0.f), pa1 = pa0, pb;
    if (avalid) {
        pa0 = *(const float4*)&X[(row0 + ar) * DD + ak];
        pa1 = *(const float4*)&X[(row0 + ar) * DD + ak + 4];
    }
    pb = *(const float4*)&W[(n0 + bn) * DD + bkk];
    As[0][ak + 0][ar] = pa0.x; As[0][ak + 1][ar] = pa0.y; As[0][ak + 2][ar] = pa0.z; As[0][ak + 3][ar] = pa0.w;
    As[0][ak + 4][ar] = pa1.x; As[0][ak + 5][ar] = pa1.y; As[0][ak + 6][ar] = pa1.z; As[0][ak + 7][ar] = pa1.w;
    Bs[0][bkk + 0][bn] = pb.x; Bs[0][bkk + 1][bn] = pb.y; Bs[0][bkk + 2][bn] = pb.z; Bs[0][bkk + 3][bn] = pb.w;
    __syncthreads();

    for (int t = 0; t < 32; t++) {
        const int cur = t & 1;
        if (t < 31) {
            const int k0 = (t + 1) * 16;
            pa0 = make_float4(0.f, 0.f, 0.f, 0.f); pa1 = pa0;
            if (avalid) {
                pa0 = *(const float4*)&X[(row0 + ar) * DD + k0 + ak];
                pa1 = *(const float4*)&X[(row0 + ar) * DD + k0 + ak + 4];
            }
            pb = *(const float4*)&W[(n0 + bn) * DD + k0 + bkk];
        }

#pragma unroll
        for (int kk = 0; kk < 16; kk++) {
            const float4 a = *(const float4*)&As[cur][kk][ty * 4];
            const float4 bv = *(const float4*)&Bs[cur][kk][tx * 4];
            const float2 mp0 = make_float2(a.x, a.y);
            const float2 mp1 = make_float2(a.z, a.w);
            const float2 d0 = make_float2(bv.x, bv.x);
            const float2 d1 = make_float2(bv.y, bv.y);
            const float2 d2 = make_float2(bv.z, bv.z);
            const float2 d3 = make_float2(bv.w, bv.w);
            acc[0][0] = ffma2(mp0, d0, acc[0][0]); acc[0][1] = ffma2(mp0, d1, acc[0][1]);
            acc[0][2] = ffma2(mp0, d2, acc[0][2]); acc[0][3] = ffma2(mp0, d3, acc[0][3]);
            acc[1][0] = ffma2(mp1, d0, acc[1][0]); acc[1][1] = ffma2(mp1, d1, acc[1][1]);
            acc[1][2] = ffma2(mp1, d2, acc[1][2]); acc[1][3] = ffma2(mp1, d3, acc[1][3]);
        }
        __syncthreads();

        if (t < 31) {
            const int nxt = cur ^ 1;
            As[nxt][ak + 0][ar] = pa0.x; As[nxt][ak + 1][ar] = pa0.y;
            As[nxt][ak + 2][ar] = pa0.z; As[nxt][ak + 3][ar] = pa0.w;
            As[nxt][ak + 4][ar] = pa1.x; As[nxt][ak + 5][ar] = pa1.y;
            As[nxt][ak + 6][ar] = pa1.z; As[nxt][ak + 7][ar] = pa1.w;
            Bs[nxt][bkk + 0][bn] = pb.x; Bs[nxt][bkk + 1][bn] = pb.y;
            Bs[nxt][bkk + 2][bn] = pb.z; Bs[nxt][bkk + 3][bn] = pb.w;
            __syncthreads();
        }
    }

    const float4 bv4 = *(const float4*)&bias[n0 + tx * 4];
#pragma unroll
    for (int mp = 0; mp < 2; mp++) {
        const int r0 = row0 + ty * 4 + 2 * mp;
        if (r0 < Mrows) {
            float4 v;
            v.x = acc[mp][0].x + bv4.x; v.y = acc[mp][1].x + bv4.y;
            v.z = acc[mp][2].x + bv4.z; v.w = acc[mp][3].x + bv4.w;
            *(float4*)&C[r0 * DD + n0 + tx * 4] = v;
        }
        if (r0 + 1 < Mrows) {
            float4 v;
            v.x = acc[mp][0].y + bv4.x; v.y = acc[mp][1].y + bv4.y;
            v.z = acc[mp][2].y + bv4.z; v.w = acc[mp][3].y + bv4.w;
            *(float4*)&C[(r0 + 1) * DD + n0 + tx * 4] = v;
        }
    }
}

// =====================================================================
// K2: fused cross-attention + sentence gate.  One block per (b, n).
// =====================================================================
__global__ void __launch_bounds__(256) cross_attn_kernel(
    const float* __restrict__ f_b, const float* __restrict__ f_w,
    const float* __restrict__ f_s)
{
    const int n = blockIdx.x, b = blockIdx.y;
    __shared__ float qs[DD];
    __shared__ float logit[24];
    __shared__ float attn[24];
    const int tid = threadIdx.x;  // 256
    const int w = tid >> 5, lane = tid & 31;

    const float* qrow = &g_q[(b * NN + n) * DD];
    for (int d = tid; d < DD; d += 256) qs[d] = qrow[d];
    __syncthreads();

    for (int l = w; l < LL; l += 8) {
        const float* krow = &g_k[(b * LL + l) * DD];
        float s = 0.f;
        for (int d = lane; d < DD; d += 32) s += qs[d] * krow[d];
#pragma unroll
        for (int o = 16; o > 0; o >>= 1) s += __shfl_xor_sync(0xffffffffu, s, o);
        if (lane == 0) logit[l] = s * SCALE;
    }
    __syncthreads();

    if (tid < 32) {
        float lg = (tid < LL) ? logit[tid] : -1e30f;
        float mx = lg;
#pragma unroll
        for (int o = 16; o > 0; o >>= 1) mx = fmaxf(mx, __shfl_xor_sync(0xffffffffu, mx, o));
        float e = (tid < LL) ? __expf(lg - mx) : 0.f;
        float s = e;
#pragma unroll
        for (int o = 16; o > 0; o >>= 1) s += __shfl_xor_sync(0xffffffffu, s, o);
        if (tid < LL) attn[tid] = e / s;
    }
    __syncthreads();

    for (int d = tid; d < DD; d += 256) {
        float acc = 0.f;
#pragma unroll
        for (int l = 0; l < LL; l++) acc += attn[l] * f_w[(b * LL + l) * DD + d];
        const float v = f_b[(b * NN + n) * DD + d] * (acc + f_s[b * DD + d]);
        g_fbq[(b * NN + n) * DD + d] = v;
    }
}

// =====================================================================
// K3: A_b logit partials = scale * f_bq @ f_bq^T.  SYMMETRIC (rt<=ct),
// K-SPLIT x2, 128 threads, double-buffered, FFMA2.
// =====================================================================
__global__ void __launch_bounds__(128) ab_logits_kernel()
{
    const int ct = blockIdx.x, rt = blockIdx.y;
    if (rt > ct) return;
    const int b = blockIdx.z >> 1, kz = blockIdx.z & 1;
    const float* X = &g_fbq[b * NN * DD];
    float* Sb = (kz == 0) ? &g_S0[b * NN * NN] : &g_S1[b * NN * NN];
    const int r0 = rt * 32, c0 = ct * 32;
    const int kbeg = kz * 256;

    __shared__ __align__(16) float As[2][16][36];
    __shared__ __align__(16) float Bs[2][16][36];
    const int tid = threadIdx.x;  // 128
    const int tx = tid & 7;       // n = tx*4
    const int ty = tid >> 3;      // m-pair: m = ty*2
    const int lr = tid >> 2;      // loader row 0..31
    const int lk = (tid & 3) * 4; // loader k offset

    float2 acc[4] = {};

    float4 pa = *(const float4*)&X[(r0 + lr) * DD + kbeg + lk];
    float4 pbv = *(const float4*)&X[(c0 + lr) * DD + kbeg + lk];
    As[0][lk + 0][lr] = pa.x; As[0][lk + 1][lr] = pa.y; As[0][lk + 2][lr] = pa.z; As[0][lk + 3][lr] = pa.w;
    Bs[0][lk + 0][lr] = pbv.x; Bs[0][lk + 1][lr] = pbv.y; Bs[0][lk + 2][lr] = pbv.z; Bs[0][lk + 3][lr] = pbv.w;
    __syncthreads();

    for (int t = 0; t < 16; t++) {
        const int cur = t & 1;
        if (t < 15) {
            const int k0 = kbeg + (t + 1) * 16;
            pa = *(const float4*)&X[(r0 + lr) * DD + k0 + lk];
            pbv = *(const float4*)&X[(c0 + lr) * DD + k0 + lk];
        }

#pragma unroll
        for (int kk = 0; kk < 16; kk++) {
            const float2 a = *(const float2*)&As[cur][kk][ty * 2];
            const float4 bv = *(const float4*)&Bs[cur][kk][tx * 4];
            acc[0] = ffma2(a, make_float2(bv.x, bv.x), acc[0]);
            acc[1] = ffma2(a, make_float2(bv.y, bv.y), acc[1]);
            acc[2] = ffma2(a, make_float2(bv.z, bv.z), acc[2]);
            acc[3] = ffma2(a, make_float2(bv.w, bv.w), acc[3]);
        }
        __syncthreads();

        if (t < 15) {
            const int nxt = cur ^ 1;
            As[nxt][lk + 0][lr] = pa.x; As[nxt][lk + 1][lr] = pa.y;
            As[nxt][lk + 2][lr] = pa.z; As[nxt][lk + 3][lr] = pa.w;
            Bs[nxt][lk + 0][lr] = pbv.x; Bs[nxt][lk + 1][lr] = pbv.y;
            Bs[nxt][lk + 2][lr] = pbv.z; Bs[nxt][lk + 3][lr] = pbv.w;
            __syncthreads();
        }
    }

#pragma unroll
    for (int h = 0; h < 2; h++) {
        const int row = r0 + ty * 2 + h;
        float4 o;
        o.x = (h ? acc[0].y : acc[0].x) * SCALE;
        o.y = (h ? acc[1].y : acc[1].x) * SCALE;
        o.z = (h ? acc[2].y : acc[2].x) * SCALE;
        o.w = (h ? acc[3].y : acc[3].x) * SCALE;
        *(float4*)&Sb[row * NN + c0 + tx * 4] = o;
        if (rt != ct) {
            Sb[(c0 + tx * 4 + 0) * NN + row] = o.x;
            Sb[(c0 + tx * 4 + 1) * NN + row] = o.y;
            Sb[(c0 + tx * 4 + 2) * NN + row] = o.z;
            Sb[(c0 + tx * 4 + 3) * NN + row] = o.w;
        }
    }
}

// =====================================================================
// K4: softmax of (S0+S1) -> g_A (rows) and g_At (transposed).
// =====================================================================
__global__ void __launch_bounds__(128) softmax_kernel()
{
    const int w = threadIdx.x >> 5, lane = threadIdx.x & 31;
    const int r = blockIdx.x * 4 + w;        // global row 0..511
    const int b = r >> 7, j = r & 127;

    const float4 s0 = *(const float4*)&g_S0[r * NN + lane * 4];
    const float4 s1 = *(const float4*)&g_S1[r * NN + lane * 4];
    float4 v;
    v.x = s0.x + s1.x; v.y = s0.y + s1.y; v.z = s0.z + s1.z; v.w = s0.w + s1.w;

    float m = fmaxf(fmaxf(v.x, v.y), fmaxf(v.z, v.w));
#pragma unroll
    for (int o = 16; o > 0; o >>= 1) m = fmaxf(m, __shfl_xor_sync(0xffffffffu, m, o));
    float4 e;
    e.x = __expf(v.x - m); e.y = __expf(v.y - m);
    e.z = __expf(v.z - m); e.w = __expf(v.w - m);
    float s = e.x + e.y + e.z + e.w;
#pragma unroll
    for (int o = 16; o > 0; o >>= 1) s += __shfl_xor_sync(0xffffffffu, s, o);
    const float inv = 1.f / s;
    e.x *= inv; e.y *= inv; e.z *= inv; e.w *= inv;

    *(float4*)&g_A[r * NN + lane * 4] = e;
    float* At = &g_At[b * NN * NN];
    At[(lane * 4 + 0) * NN + j] = e.x;
    At[(lane * 4 + 1) * NN + j] = e.y;
    At[(lane * 4 + 2) * NN + j] = e.z;
    At[(lane * 4 + 3) * NN + j] = e.w;
}

// =====================================================================
// K5: fused final, j-PAIRED:  block (jp, b) computes j0=2jp, j1=2jp+1.
// 512 threads, 4 groups of 128:
//   Phase A (f_bb): group g sums m in [g*32,g*32+32) for BOTH j0,j1
//                   (each f_b load feeds 2 FMAs -> half L2 traffic)
//   Phase B (f_bm): group g: jj=g>>1 selects j, par=g&1 splits i;
//                   sigmoid via MUFU.TANH (1 MUFU/elem)
// Combine partials in smem; groups write, tid<256 reduces + writes out.
// =====================================================================
__global__ void __launch_bounds__(512) final_kernel(
    const float* __restrict__ f_b, const float* __restrict__ f_s,
    const float* __restrict__ f_m, float* __restrict__ out)
{
    const int jp = blockIdx.x, b = blockIdx.y;
    const int j0 = jp * 2;

    __shared__ float arow0[NN], arow1[NN], acol0[NN], acol1[NN];
    __shared__ __align__(16) float4 rA0[4][128];
    __shared__ __align__(16) float4 rA1[4][128];
    __shared__ __align__(16) float4 rB[4][128];

    const int tid = threadIdx.x;   // 512
    const int q = tid & 127;
    const int g = tid >> 7;        // group 0..3

    // load A row/col vectors (coalesced, one segment per group)
    {
        const float* src;
        float* dst;
        if (g == 0)      { src = &g_A[(b * NN + j0) * NN];           dst = arow0; }
        else if (g == 1) { src = &g_A[(b * NN + j0 + 1) * NN];       dst = arow1; }
        else if (g == 2) { src = &g_At[b * NN * NN + j0 * NN];       dst = acol0; }
        else             { src = &g_At[b * NN * NN + (j0 + 1) * NN]; dst = acol1; }
        dst[q] = src[q];
    }
    __syncthreads();

    const int d4 = q * 4;
    float4 fsh = *(const float4*)&f_s[b * DD + d4];   // halved for tanh form
    fsh.x *= 0.5f; fsh.y *= 0.5f; fsh.z *= 0.5f; fsh.w *= 0.5f;

    // ---- Phase A: f_bb partial over m-quarter, both j's ----
    float4 a0 = make_float4(0.f, 0.f, 0.f, 0.f);
    float4 a1 = a0;
    {
        const float* fbb = f_b + (size_t)b * NN * DD;
#pragma unroll 4
        for (int m = g * 32; m < g * 32 + 32; m++) {
            const float4 v = *(const float4*)&fbb[(size_t)m * DD + d4];
            const float w0 = arow0[m], w1 = arow1[m];
            a0.x += w0 * v.x; a0.y += w0 * v.y; a0.z += w0 * v.z; a0.w += w0 * v.w;
            a1.x += w1 * v.x; a1.y += w1 * v.y; a1.z += w1 * v.z; a1.w += w1 * v.w;
        }
    }

    // ---- Phase B: f_bm partial (i-parity split, one j per group) ----
    const int jj = g >> 1, par = g & 1;
    const float* ac = jj ? acol1 : acol0;
    const float* fm = f_m + ((size_t)(b * NN * NN) + j0 + jj) * DD;
    float4 bm = make_float4(0.f, 0.f, 0.f, 0.f);
#pragma unroll 4
    for (int i = par; i < NN; i += 2) {
        const float a = ac[i];
        const float4 v = *(const float4*)&fm[(size_t)i * NN * DD + d4];
        // gate*v = v * (0.5*tanh(0.5*v*fs) + 0.5)
        const float g0 = fmaf(0.5f, fast_tanh(v.x * fsh.x), 0.5f);
        const float g1 = fmaf(0.5f, fast_tanh(v.y * fsh.y), 0.5f);
        const float g2 = fmaf(0.5f, fast_tanh(v.z * fsh.z), 0.5f);
        const float g3 = fmaf(0.5f, fast_tanh(v.w * fsh.w), 0.5f);
        bm.x += a * g0 * v.x;
        bm.y += a * g1 * v.y;
        bm.z += a * g2 * v.z;
        bm.w += a * g3 * v.w;
    }

    rA0[g][q] = a0; rA1[g][q] = a1; rB[g][q] = bm;
    __syncthreads();

    // ---- combine + residual + store: tid<256, jj2 = tid>>7 selects j ----
    if (tid < 256) {
        const int jj2 = tid >> 7;
        const int q2 = tid & 127;
        const int dd4 = q2 * 4;
        float4 s = make_float4(0.f, 0.f, 0.f, 0.f);
#pragma unroll
        for (int gg = 0; gg < 4; gg++) {
            const float4 pa = jj2 ? rA1[gg][q2] : rA0[gg][q2];
            s.x += pa.x; s.y += pa.y; s.z += pa.z; s.w += pa.w;
        }
        const float4 b0 = rB[jj2 * 2][q2];
        const float4 b1 = rB[jj2 * 2 + 1][q2];
        const size_t o = (size_t)(b * NN + j0 + jj2) * DD;
        const float4 fb4 = *(const float4*)&f_b[o + dd4];
        float4 r;
        r.x = s.x + b0.x + b1.x + fb4.x;
        r.y = s.y + b0.y + b1.y + fb4.y;
        r.z = s.z + b0.z + b1.z + fb4.z;
        r.w = s.w + b0.w + b1.w + fb4.w;
        *(float4*)&out[o + dd4] = r;
    }
}

// =====================================================================
extern "C" void kernel_launch(void* const* d_in, const int* in_sizes, int n_in,
                              void* d_out, int out_size)
{
    const float* f_b = (const float*)d_in[0];
    const float* f_w = (const float*)d_in[1];
    const float* f_s = (const float*)d_in[2];
    const float* f_m = (const float*)d_in[3];
    const float* Wq  = (const float*)d_in[4];
    const float* bq  = (const float*)d_in[5];
    const float* Wk  = (const float*)d_in[6];
    const float* bk  = (const float*)d_in[7];
    float* out = (float*)d_out;

    proj_kernel<<<dim3(16, 10), 128>>>(f_b, f_w, Wq, bq, Wk, bk);
    cross_attn_kernel<<<dim3(NN, BB), 256>>>(f_b, f_w, f_s);
    ab_logits_kernel<<<dim3(4, 4, BB * 2), 128>>>();
    softmax_kernel<<<128, 128>>>();
    final_kernel<<<dim3(NN / 2, BB), 512>>>(f_b, f_s, f_m, out);
}